// round 8
// baseline (speedup 1.0000x reference)
#include <cuda_runtime.h>
#include <cstdint>

#define DD 128
#define MAXROWS (2*50000)
#define MAXN 50001
#define MAXE 800000

// scratch (__device__ globals — allocation-free rule)
__device__ float g_m[MAXROWS * DD];
__device__ float g_agg[MAXROWS * DD];
__device__ int   g_cnt[MAXN];
__device__ int   g_base[MAXN];
__device__ int   g_sorted[MAXE];

// ---------------------------------------------------------------------------
// helpers
// ---------------------------------------------------------------------------
__device__ __forceinline__ float to_tf32(float x) {
    uint32_t u;
    asm("cvt.rna.tf32.f32 %0, %1;" : "=r"(u) : "f"(x));
    return __uint_as_float(u);
}
__device__ __forceinline__ void split_tf32(float x, float& hi, float& lo) {
    hi = to_tf32(x);
    lo = to_tf32(x - hi);
}
__device__ __forceinline__ void mma_tf32(float* c, const float* a, const float* b) {
    asm volatile(
        "mma.sync.aligned.m16n8k8.row.col.f32.tf32.tf32.f32 "
        "{%0,%1,%2,%3}, {%4,%5,%6,%7}, {%8,%9}, {%0,%1,%2,%3};"
        : "+f"(c[0]), "+f"(c[1]), "+f"(c[2]), "+f"(c[3])
        : "r"(__float_as_uint(a[0])), "r"(__float_as_uint(a[1])),
          "r"(__float_as_uint(a[2])), "r"(__float_as_uint(a[3])),
          "r"(__float_as_uint(b[0])), "r"(__float_as_uint(b[1])));
}

// smem layout (floats), padded stride 36 — R5-proven layout, 128-row A tile
#define SA_STR 36
#define OF_ASH 0
#define OF_ASL (128 * SA_STR)
#define OF_BSH (2 * 128 * SA_STR)
#define OF_BSL (OF_BSH + 128 * SA_STR)
#define SM_FLOATS (OF_BSL + 128 * SA_STR)
#define SM_BYTES (SM_FLOATS * 4)       // 73728

// ============================================================================
// Edge sort (counting sort by target)
// ============================================================================
__global__ __launch_bounds__(256) void hist_k(const int* __restrict__ etgt,
                                              int* __restrict__ cnt, int E)
{
    int e = blockIdx.x * blockDim.x + threadIdx.x;
    if (e < E) atomicAdd(&cnt[etgt[e]], 1);
}

__global__ __launch_bounds__(1024) void exscan_k(const int* __restrict__ cnt,
                                                 int* __restrict__ base, int n)
{
    __shared__ int ws[32];
    __shared__ int carry_s;
    const int tid = threadIdx.x;
    const int lane = tid & 31, wid = tid >> 5;
    if (tid == 0) carry_s = 0;
    __syncthreads();

    for (int chunk = 0; chunk < n; chunk += 1024) {
        const int i = chunk + tid;
        const int x = (i < n) ? cnt[i] : 0;
        int v = x;
        #pragma unroll
        for (int o = 1; o < 32; o <<= 1) {
            int t = __shfl_up_sync(0xffffffffu, v, o);
            if (lane >= o) v += t;
        }
        if (lane == 31) ws[wid] = v;
        __syncthreads();
        if (wid == 0) {
            int w = ws[lane];
            #pragma unroll
            for (int o = 1; o < 32; o <<= 1) {
                int t = __shfl_up_sync(0xffffffffu, w, o);
                if (lane >= o) w += t;
            }
            ws[lane] = w;
        }
        __syncthreads();
        const int woff = (wid > 0) ? ws[wid - 1] : 0;
        const int carry = carry_s;
        const int incl = v + woff + carry;
        if (i < n) base[i] = incl - x;
        __syncthreads();
        if (tid == 1023) carry_s = incl;
        __syncthreads();
    }
}

__global__ __launch_bounds__(256) void fill_k(
    const int* __restrict__ esrc, const int* __restrict__ etgt,
    const int* __restrict__ erel, int* __restrict__ base,
    int* __restrict__ sorted, int E)
{
    int e = blockIdx.x * blockDim.x + threadIdx.x;
    if (e >= E) return;
    const int t = etgt[e];
    const int pos = atomicAdd(&base[t], 1);
    sorted[pos] = esrc[e] | (erel[e] << 17);
}

// ---------------------------------------------------------------------------
// mma over one staged K=32 chunk; warp tile 64x32 (mt 0..3)
// ---------------------------------------------------------------------------
__device__ __forceinline__ void mma_chunk(const float* Ash, const float* Asl,
                                          const float* Bsh, const float* Bsl,
                                          int m0, int n0, int g, int q,
                                          float c[4][4][4])
{
    #pragma unroll
    for (int ks = 0; ks < 4; ++ks) {
        const int kc = ks * 8;
        float bh[4][2], bl[4][2];
        #pragma unroll
        for (int nt = 0; nt < 4; ++nt) {
            const int rb = (n0 + nt * 8 + g) * SA_STR + kc + q;
            bh[nt][0] = Bsh[rb];
            bh[nt][1] = Bsh[rb + 4];
            bl[nt][0] = Bsl[rb];
            bl[nt][1] = Bsl[rb + 4];
        }
        #pragma unroll
        for (int mt = 0; mt < 4; ++mt) {
            const int rb = (m0 + mt * 16 + g) * SA_STR + kc + q;
            float ah[4], al[4];
            ah[0] = Ash[rb];
            ah[1] = Ash[rb + 8 * SA_STR];
            ah[2] = Ash[rb + 4];
            ah[3] = Ash[rb + 8 * SA_STR + 4];
            al[0] = Asl[rb];
            al[1] = Asl[rb + 8 * SA_STR];
            al[2] = Asl[rb + 4];
            al[3] = Asl[rb + 8 * SA_STR + 4];
            #pragma unroll
            for (int nt = 0; nt < 4; ++nt) {
                mma_tf32(c[mt][nt], ah, bh[nt]);
                mma_tf32(c[mt][nt], ah, bl[nt]);
                mma_tf32(c[mt][nt], al, bh[nt]);
            }
        }
    }
}

// ============================================================================
// Kernel 1: m = h @ W_msg^T  (tf32x3, 128-row tile, R5 layout)
// 8 warps: warp_m (2) x warp_n (4); warp tile 64 x 32
// ============================================================================
__global__ __launch_bounds__(256) void msg_gemm_mma(
    const float* __restrict__ h, const float* __restrict__ W,
    float* __restrict__ m, int rows)
{
    extern __shared__ float sm[];
    float* Ash = sm + OF_ASH;
    float* Asl = sm + OF_ASL;
    float* Bsh = sm + OF_BSH;
    float* Bsl = sm + OF_BSL;

    const int tid = threadIdx.x;
    const int lane = tid & 31, wid = tid >> 5;
    const int g = lane >> 2, q = lane & 3;
    const int m0 = (wid >> 2) * 64, n0 = (wid & 3) * 32;
    const int row0 = blockIdx.x * 128;

    const float4* h4 = (const float4*)h;
    const float4* W4 = (const float4*)W;

    float c[4][4][4];
    #pragma unroll
    for (int mt = 0; mt < 4; ++mt)
        #pragma unroll
        for (int nt = 0; nt < 4; ++nt)
            #pragma unroll
            for (int k = 0; k < 4; ++k) c[mt][nt][k] = 0.f;

    for (int ch = 0; ch < 4; ++ch) {
        // stage A (128 x 32)
        #pragma unroll
        for (int i = tid; i < 1024; i += 256) {
            const int r = i >> 3, j4 = i & 7;
            const int gr = row0 + r;
            float4 v = (gr < rows) ? h4[gr * 32 + ch * 8 + j4]
                                   : make_float4(0.f, 0.f, 0.f, 0.f);
            float4 hi, lo;
            split_tf32(v.x, hi.x, lo.x);
            split_tf32(v.y, hi.y, lo.y);
            split_tf32(v.z, hi.z, lo.z);
            split_tf32(v.w, hi.w, lo.w);
            *(float4*)&Ash[r * SA_STR + j4 * 4] = hi;
            *(float4*)&Asl[r * SA_STR + j4 * 4] = lo;
        }
        // stage B (128 x 32)
        #pragma unroll
        for (int i = tid; i < 1024; i += 256) {
            const int r = i >> 3, j4 = i & 7;
            float4 w = W4[r * 32 + ch * 8 + j4];
            float4 hi, lo;
            split_tf32(w.x, hi.x, lo.x);
            split_tf32(w.y, hi.y, lo.y);
            split_tf32(w.z, hi.z, lo.z);
            split_tf32(w.w, hi.w, lo.w);
            *(float4*)&Bsh[r * SA_STR + j4 * 4] = hi;
            *(float4*)&Bsl[r * SA_STR + j4 * 4] = lo;
        }
        __syncthreads();
        mma_chunk(Ash, Asl, Bsh, Bsl, m0, n0, g, q, c);
        __syncthreads();
    }

    // epilogue
    #pragma unroll
    for (int mt = 0; mt < 4; ++mt) {
        const int rlo = row0 + m0 + mt * 16 + g;
        const int rhi = rlo + 8;
        #pragma unroll
        for (int nt = 0; nt < 4; ++nt) {
            const int col = n0 + nt * 8 + q * 2;
            if (rlo < rows)
                *(float2*)&m[rlo * DD + col] = make_float2(c[mt][nt][0], c[mt][nt][1]);
            if (rhi < rows)
                *(float2*)&m[rhi * DD + col] = make_float2(c[mt][nt][2], c[mt][nt][3]);
        }
    }
}

// ============================================================================
// Kernel 2: CSR gather. One warp per target node, both batches, no atomics.
// ============================================================================
__global__ __launch_bounds__(256) void gather_csr(
    const float* __restrict__ m, const float* __restrict__ rel_emb,
    const int* __restrict__ base, const int* __restrict__ sorted,
    float* __restrict__ agg, int N, int ND)
{
    const int nid = blockIdx.x * 8 + (threadIdx.x >> 5);
    if (nid >= N) return;
    const int lane = threadIdx.x & 31;

    const int start = (nid == 0) ? 0 : __ldg(&base[nid - 1]);
    const int end = __ldg(&base[nid]);

    const float4* m4 = (const float4*)m;
    const float4* r4 = (const float4*)rel_emb;
    const int ND4 = ND / 4;

    float4 a0 = make_float4(0.f,0.f,0.f,0.f);
    float4 a1 = make_float4(0.f,0.f,0.f,0.f);

    int i = start;
    for (; i + 1 < end; i += 2) {
        const int pA = __ldg(&sorted[i]);
        const int pB = __ldg(&sorted[i + 1]);
        const int sA = pA & 0x1FFFF, rA = pA >> 17;
        const int sB = pB & 0x1FFFF, rB = pB >> 17;
        const float4 rvA = r4[rA * 32 + lane];
        const float4 m0A = m4[sA * 32 + lane];
        const float4 m1A = m4[ND4 + sA * 32 + lane];
        const float4 rvB = r4[rB * 32 + lane];
        const float4 m0B = m4[sB * 32 + lane];
        const float4 m1B = m4[ND4 + sB * 32 + lane];
        a0.x = fmaf(m0A.x, rvA.x, a0.x); a0.y = fmaf(m0A.y, rvA.y, a0.y);
        a0.z = fmaf(m0A.z, rvA.z, a0.z); a0.w = fmaf(m0A.w, rvA.w, a0.w);
        a1.x = fmaf(m1A.x, rvA.x, a1.x); a1.y = fmaf(m1A.y, rvA.y, a1.y);
        a1.z = fmaf(m1A.z, rvA.z, a1.z); a1.w = fmaf(m1A.w, rvA.w, a1.w);
        a0.x = fmaf(m0B.x, rvB.x, a0.x); a0.y = fmaf(m0B.y, rvB.y, a0.y);
        a0.z = fmaf(m0B.z, rvB.z, a0.z); a0.w = fmaf(m0B.w, rvB.w, a0.w);
        a1.x = fmaf(m1B.x, rvB.x, a1.x); a1.y = fmaf(m1B.y, rvB.y, a1.y);
        a1.z = fmaf(m1B.z, rvB.z, a1.z); a1.w = fmaf(m1B.w, rvB.w, a1.w);
    }
    if (i < end) {
        const int p = __ldg(&sorted[i]);
        const int s = p & 0x1FFFF, r = p >> 17;
        const float4 rv = r4[r * 32 + lane];
        const float4 m0 = m4[s * 32 + lane];
        const float4 m1 = m4[ND4 + s * 32 + lane];
        a0.x = fmaf(m0.x, rv.x, a0.x); a0.y = fmaf(m0.y, rv.y, a0.y);
        a0.z = fmaf(m0.z, rv.z, a0.z); a0.w = fmaf(m0.w, rv.w, a0.w);
        a1.x = fmaf(m1.x, rv.x, a1.x); a1.y = fmaf(m1.y, rv.y, a1.y);
        a1.z = fmaf(m1.z, rv.z, a1.z); a1.w = fmaf(m1.w, rv.w, a1.w);
    }

    float4* agg4 = (float4*)agg;
    agg4[nid * 32 + lane] = a0;
    agg4[ND4 + nid * 32 + lane] = a1;
}

// ============================================================================
// Kernel 3: upd = relu([h|agg] @ W_upd^T + b); out = LN(h + upd)
// tf32x3, 128-row tile, K=256 in 8 chunks (0-3: h, 4-7: agg)
// ============================================================================
__global__ __launch_bounds__(256) void update_ln_mma(
    const float* __restrict__ h, const float* __restrict__ agg,
    const float* __restrict__ Wupd, const float* __restrict__ bupd,
    const float* __restrict__ lns, const float* __restrict__ lnb,
    float* __restrict__ out, int rows)
{
    extern __shared__ float sm[];
    float* Ash = sm + OF_ASH;
    float* Asl = sm + OF_ASL;
    float* Bsh = sm + OF_BSH;
    float* Bsl = sm + OF_BSL;

    const int tid = threadIdx.x;
    const int lane = tid & 31, wid = tid >> 5;
    const int g = lane >> 2, q = lane & 3;
    const int m0 = (wid >> 2) * 64, n0 = (wid & 3) * 32;
    const int warp_n = wid & 3;
    const int row0 = blockIdx.x * 128;

    const float4* h4 = (const float4*)h;
    const float4* a4 = (const float4*)agg;
    const float4* W4 = (const float4*)Wupd;    // row stride 64 float4

    float c[4][4][4];
    #pragma unroll
    for (int mt = 0; mt < 4; ++mt)
        #pragma unroll
        for (int nt = 0; nt < 4; ++nt)
            #pragma unroll
            for (int k = 0; k < 4; ++k) c[mt][nt][k] = 0.f;

    for (int ch = 0; ch < 8; ++ch) {
        const float4* src4 = (ch < 4) ? h4 : a4;
        const int scol8 = (ch & 3) * 8;
        #pragma unroll
        for (int i = tid; i < 1024; i += 256) {
            const int r = i >> 3, j4 = i & 7;
            const int gr = row0 + r;
            float4 v = (gr < rows) ? src4[gr * 32 + scol8 + j4]
                                   : make_float4(0.f, 0.f, 0.f, 0.f);
            float4 hi, lo;
            split_tf32(v.x, hi.x, lo.x);
            split_tf32(v.y, hi.y, lo.y);
            split_tf32(v.z, hi.z, lo.z);
            split_tf32(v.w, hi.w, lo.w);
            *(float4*)&Ash[r * SA_STR + j4 * 4] = hi;
            *(float4*)&Asl[r * SA_STR + j4 * 4] = lo;
        }
        #pragma unroll
        for (int i = tid; i < 1024; i += 256) {
            const int r = i >> 3, j4 = i & 7;
            float4 w = W4[r * 64 + ch * 8 + j4];
            float4 hi, lo;
            split_tf32(w.x, hi.x, lo.x);
            split_tf32(w.y, hi.y, lo.y);
            split_tf32(w.z, hi.z, lo.z);
            split_tf32(w.w, hi.w, lo.w);
            *(float4*)&Bsh[r * SA_STR + j4 * 4] = hi;
            *(float4*)&Bsl[r * SA_STR + j4 * 4] = lo;
        }
        __syncthreads();
        mma_chunk(Ash, Asl, Bsh, Bsl, m0, n0, g, q, c);
        __syncthreads();
    }

    // ---- epilogue: v = relu(C + b) + h, LN across row ----
    float2* red = (float2*)sm;          // red[row(128)][warp_n(4)]

    float2 bias[4], lsc[4], lbi[4];
    #pragma unroll
    for (int nt = 0; nt < 4; ++nt) {
        const int col = n0 + nt * 8 + q * 2;
        bias[nt] = *(const float2*)&bupd[col];
        lsc[nt]  = *(const float2*)&lns[col];
        lbi[nt]  = *(const float2*)&lnb[col];
    }

    float s1v[4][2], s2v[4][2];
    #pragma unroll
    for (int mt = 0; mt < 4; ++mt) {
        const int rlo = row0 + m0 + mt * 16 + g;
        const int rhi = rlo + 8;
        float p1lo = 0.f, p2lo = 0.f, p1hi = 0.f, p2hi = 0.f;
        #pragma unroll
        for (int nt = 0; nt < 4; ++nt) {
            const int col = n0 + nt * 8 + q * 2;
            float2 hlo = (rlo < rows) ? *(const float2*)&h[rlo * DD + col]
                                      : make_float2(0.f, 0.f);
            float2 hhi = (rhi < rows) ? *(const float2*)&h[rhi * DD + col]
                                      : make_float2(0.f, 0.f);
            float v0 = fmaxf(c[mt][nt][0] + bias[nt].x, 0.f) + hlo.x;
            float v1 = fmaxf(c[mt][nt][1] + bias[nt].y, 0.f) + hlo.y;
            float v2 = fmaxf(c[mt][nt][2] + bias[nt].x, 0.f) + hhi.x;
            float v3 = fmaxf(c[mt][nt][3] + bias[nt].y, 0.f) + hhi.y;
            c[mt][nt][0] = v0; c[mt][nt][1] = v1;
            c[mt][nt][2] = v2; c[mt][nt][3] = v3;
            p1lo += v0 + v1;  p2lo += v0*v0 + v1*v1;
            p1hi += v2 + v3;  p2hi += v2*v2 + v3*v3;
        }
        s1v[mt][0] = p1lo; s2v[mt][0] = p2lo;
        s1v[mt][1] = p1hi; s2v[mt][1] = p2hi;
    }
    #pragma unroll
    for (int mt = 0; mt < 4; ++mt)
        #pragma unroll
        for (int hf = 0; hf < 2; ++hf) {
            float s1 = s1v[mt][hf], s2 = s2v[mt][hf];
            s1 += __shfl_xor_sync(0xffffffffu, s1, 1);
            s2 += __shfl_xor_sync(0xffffffffu, s2, 1);
            s1 += __shfl_xor_sync(0xffffffffu, s1, 2);
            s2 += __shfl_xor_sync(0xffffffffu, s2, 2);
            if (q == 0) {
                const int rl = m0 + mt * 16 + hf * 8 + g;
                red[rl * 4 + warp_n] = make_float2(s1, s2);
            }
        }
    __syncthreads();

    #pragma unroll
    for (int mt = 0; mt < 4; ++mt) {
        #pragma unroll
        for (int hf = 0; hf < 2; ++hf) {
            const int rl = m0 + mt * 16 + hf * 8 + g;
            const int gr = row0 + rl;
            float S1 = 0.f, S2 = 0.f;
            #pragma unroll
            for (int w = 0; w < 4; ++w) {
                float2 p = red[rl * 4 + w];
                S1 += p.x; S2 += p.y;
            }
            const float mu  = S1 * (1.f / 128.f);
            const float var = S2 * (1.f / 128.f) - mu * mu;
            const float rs  = rsqrtf(var + 1e-5f);
            if (gr < rows) {
                #pragma unroll
                for (int nt = 0; nt < 4; ++nt) {
                    const int col = n0 + nt * 8 + q * 2;
                    const float v0 = c[mt][nt][hf * 2 + 0];
                    const float v1 = c[mt][nt][hf * 2 + 1];
                    float2 o;
                    o.x = (v0 - mu) * rs * lsc[nt].x + lbi[nt].x;
                    o.y = (v1 - mu) * rs * lsc[nt].y + lbi[nt].y;
                    *(float2*)&out[gr * DD + col] = o;
                }
            }
        }
    }
}

// ============================================================================
// host
// ============================================================================
extern "C" void kernel_launch(void* const* d_in, const int* in_sizes, int n_in,
                              void* d_out, int out_size)
{
    const float* h    = (const float*)d_in[0];
    const float* Wmsg = (const float*)d_in[1];
    const float* rel  = (const float*)d_in[2];
    const float* Wupd = (const float*)d_in[3];
    const float* bupd = (const float*)d_in[4];
    const float* lns  = (const float*)d_in[5];
    const float* lnb  = (const float*)d_in[6];
    const int*   esrc = (const int*)d_in[7];
    const int*   etgt = (const int*)d_in[8];
    const int*   erel = (const int*)d_in[9];
    float* out = (float*)d_out;

    const int E    = in_sizes[7];
    const int rows = in_sizes[0] / DD;     // B*N
    const int N    = rows / 2;
    const int ND   = N * DD;
    const int tiles = (rows + 127) / 128;

    void *pm, *pa, *pc, *pb, *ps;
    cudaGetSymbolAddress(&pm, g_m);
    cudaGetSymbolAddress(&pa, g_agg);
    cudaGetSymbolAddress(&pc, g_cnt);
    cudaGetSymbolAddress(&pb, g_base);
    cudaGetSymbolAddress(&ps, g_sorted);
    float* d_m    = (float*)pm;
    float* d_agg  = (float*)pa;
    int*   d_cnt  = (int*)pc;
    int*   d_base = (int*)pb;
    int*   d_sort = (int*)ps;

    cudaFuncSetAttribute(msg_gemm_mma,
        cudaFuncAttributeMaxDynamicSharedMemorySize, SM_BYTES);
    cudaFuncSetAttribute(update_ln_mma,
        cudaFuncAttributeMaxDynamicSharedMemorySize, SM_BYTES);

    // edge sort (counting sort by target)
    cudaMemsetAsync(d_cnt, 0, (size_t)N * sizeof(int), 0);
    hist_k<<<(E + 255) / 256, 256>>>(etgt, d_cnt, E);
    exscan_k<<<1, 1024>>>(d_cnt, d_base, N);
    fill_k<<<(E + 255) / 256, 256>>>(esrc, etgt, erel, d_base, d_sort, E);

    // m = h @ W_msg^T
    msg_gemm_mma<<<tiles, 256, SM_BYTES>>>(h, Wmsg, d_m, rows);

    // agg[t] = sum_{e: tgt=t} m[src_e] * rel_emb[rel_e]
    gather_csr<<<(N + 7) / 8, 256>>>(d_m, rel, d_base, d_sort, d_agg, N, ND);

    // update + residual + layernorm
    update_ln_mma<<<tiles, 256, SM_BYTES>>>(h, d_agg, Wupd, bupd, lns, lnb, out, rows);
}

// round 9
// speedup vs baseline: 1.1670x; 1.1670x over previous
#include <cuda_runtime.h>
#include <cstdint>

#define DD 128
#define MAXROWS (2*50000)
#define MAXN 50001
#define MAXE 800000

// scratch (__device__ globals — allocation-free rule)
__device__ float g_m[MAXROWS * DD];
__device__ float g_agg[MAXROWS * DD];
__device__ int   g_cnt[MAXN];
__device__ int   g_base[MAXN];
__device__ int   g_sorted[MAXE];

// ---------------------------------------------------------------------------
// helpers
// ---------------------------------------------------------------------------
__device__ __forceinline__ float to_tf32(float x) {
    uint32_t u;
    asm("cvt.rna.tf32.f32 %0, %1;" : "=r"(u) : "f"(x));
    return __uint_as_float(u);
}
__device__ __forceinline__ void split_tf32(float x, float& hi, float& lo) {
    hi = to_tf32(x);
    lo = to_tf32(x - hi);
}
__device__ __forceinline__ void mma_tf32(float* c, const float* a, const float* b) {
    asm volatile(
        "mma.sync.aligned.m16n8k8.row.col.f32.tf32.tf32.f32 "
        "{%0,%1,%2,%3}, {%4,%5,%6,%7}, {%8,%9}, {%0,%1,%2,%3};"
        : "+f"(c[0]), "+f"(c[1]), "+f"(c[2]), "+f"(c[3])
        : "r"(__float_as_uint(a[0])), "r"(__float_as_uint(a[1])),
          "r"(__float_as_uint(a[2])), "r"(__float_as_uint(a[3])),
          "r"(__float_as_uint(b[0])), "r"(__float_as_uint(b[1])));
}

// smem layout (floats), padded stride 36 — R5-proven 64-row tile
#define SA_STR 36
#define OF_ASH 0
#define OF_ASL (64 * SA_STR)
#define OF_BSH (2 * 64 * SA_STR)
#define OF_BSL (OF_BSH + 128 * SA_STR)
#define SM_FLOATS (OF_BSL + 128 * SA_STR)
#define SM_BYTES (SM_FLOATS * 4)       // 55296

// ============================================================================
// Edge sort (counting sort by target)
// ============================================================================
__global__ __launch_bounds__(256) void hist_k(const int* __restrict__ etgt,
                                              int* __restrict__ cnt, int E)
{
    int e = blockIdx.x * blockDim.x + threadIdx.x;
    if (e < E) atomicAdd(&cnt[etgt[e]], 1);
}

__global__ __launch_bounds__(1024) void exscan_k(const int* __restrict__ cnt,
                                                 int* __restrict__ base, int n)
{
    __shared__ int ws[32];
    __shared__ int carry_s;
    const int tid = threadIdx.x;
    const int lane = tid & 31, wid = tid >> 5;
    if (tid == 0) carry_s = 0;
    __syncthreads();

    for (int chunk = 0; chunk < n; chunk += 1024) {
        const int i = chunk + tid;
        const int x = (i < n) ? cnt[i] : 0;
        int v = x;
        #pragma unroll
        for (int o = 1; o < 32; o <<= 1) {
            int t = __shfl_up_sync(0xffffffffu, v, o);
            if (lane >= o) v += t;
        }
        if (lane == 31) ws[wid] = v;
        __syncthreads();
        if (wid == 0) {
            int w = ws[lane];
            #pragma unroll
            for (int o = 1; o < 32; o <<= 1) {
                int t = __shfl_up_sync(0xffffffffu, w, o);
                if (lane >= o) w += t;
            }
            ws[lane] = w;
        }
        __syncthreads();
        const int woff = (wid > 0) ? ws[wid - 1] : 0;
        const int carry = carry_s;
        const int incl = v + woff + carry;
        if (i < n) base[i] = incl - x;
        __syncthreads();
        if (tid == 1023) carry_s = incl;
        __syncthreads();
    }
}

__global__ __launch_bounds__(256) void fill_k(
    const int* __restrict__ esrc, const int* __restrict__ etgt,
    const int* __restrict__ erel, int* __restrict__ base,
    int* __restrict__ sorted, int E)
{
    int e = blockIdx.x * blockDim.x + threadIdx.x;
    if (e >= E) return;
    const int t = etgt[e];
    const int pos = atomicAdd(&base[t], 1);
    sorted[pos] = esrc[e] | (erel[e] << 17);
}

// ---------------------------------------------------------------------------
// split+store helpers (R5 mapping: thread i covers r=i>>3, j4=i&7 per 256-step)
// ---------------------------------------------------------------------------
__device__ __forceinline__ void store_split_A(float* Ash, float* Asl,
                                              int i, float4 v)
{
    const int r = i >> 3, j4 = i & 7;
    float4 hi, lo;
    split_tf32(v.x, hi.x, lo.x);
    split_tf32(v.y, hi.y, lo.y);
    split_tf32(v.z, hi.z, lo.z);
    split_tf32(v.w, hi.w, lo.w);
    *(float4*)&Ash[r * SA_STR + j4 * 4] = hi;
    *(float4*)&Asl[r * SA_STR + j4 * 4] = lo;
}

// ---------------------------------------------------------------------------
// mma over one staged K=32 chunk; warp tile 32x32 (R5)
// ---------------------------------------------------------------------------
__device__ __forceinline__ void mma_chunk(const float* Ash, const float* Asl,
                                          const float* Bsh, const float* Bsl,
                                          int m0, int n0, int g, int q,
                                          float c[2][4][4])
{
    #pragma unroll
    for (int ks = 0; ks < 4; ++ks) {
        const int kc = ks * 8;
        float ah[2][4], al[2][4], bh[4][2], bl[4][2];
        #pragma unroll
        for (int mt = 0; mt < 2; ++mt) {
            const int rb = (m0 + mt * 16 + g) * SA_STR + kc + q;
            ah[mt][0] = Ash[rb];
            ah[mt][1] = Ash[rb + 8 * SA_STR];
            ah[mt][2] = Ash[rb + 4];
            ah[mt][3] = Ash[rb + 8 * SA_STR + 4];
            al[mt][0] = Asl[rb];
            al[mt][1] = Asl[rb + 8 * SA_STR];
            al[mt][2] = Asl[rb + 4];
            al[mt][3] = Asl[rb + 8 * SA_STR + 4];
        }
        #pragma unroll
        for (int nt = 0; nt < 4; ++nt) {
            const int rb = (n0 + nt * 8 + g) * SA_STR + kc + q;
            bh[nt][0] = Bsh[rb];
            bh[nt][1] = Bsh[rb + 4];
            bl[nt][0] = Bsl[rb];
            bl[nt][1] = Bsl[rb + 4];
        }
        #pragma unroll
        for (int mt = 0; mt < 2; ++mt)
            #pragma unroll
            for (int nt = 0; nt < 4; ++nt) {
                mma_tf32(c[mt][nt], ah[mt], bh[nt]);
                mma_tf32(c[mt][nt], ah[mt], bl[nt]);
                mma_tf32(c[mt][nt], al[mt], bh[nt]);
            }
    }
}

// ============================================================================
// Kernel 1: m = h @ W_msg^T  (tf32x3, R5 config + register-prefetch pipeline)
// ============================================================================
__global__ __launch_bounds__(256) void msg_gemm_mma(
    const float* __restrict__ h, const float* __restrict__ W,
    float* __restrict__ m, int rows)
{
    extern __shared__ float sm[];
    float* Ash = sm + OF_ASH;
    float* Asl = sm + OF_ASL;
    float* Bsh = sm + OF_BSH;
    float* Bsl = sm + OF_BSL;

    const int tid = threadIdx.x;
    const int lane = tid & 31, wid = tid >> 5;
    const int g = lane >> 2, q = lane & 3;
    const int m0 = (wid >> 2) * 32, n0 = (wid & 3) * 32;
    const int row0 = blockIdx.x * 64;

    const float4* h4 = (const float4*)h;
    const float4* W4 = (const float4*)W;

    float c[2][4][4];
    #pragma unroll
    for (int mt = 0; mt < 2; ++mt)
        #pragma unroll
        for (int nt = 0; nt < 4; ++nt)
            #pragma unroll
            for (int k = 0; k < 4; ++k) c[mt][nt][k] = 0.f;

    float4 pa[2], pb[4];
    // prefetch chunk 0
    #pragma unroll
    for (int u = 0; u < 2; ++u) {
        const int i = tid + u * 256;
        const int gr = row0 + (i >> 3);
        pa[u] = (gr < rows) ? h4[gr * 32 + (i & 7)]
                            : make_float4(0.f, 0.f, 0.f, 0.f);
    }
    #pragma unroll
    for (int u = 0; u < 4; ++u) {
        const int i = tid + u * 256;
        pb[u] = W4[(i >> 3) * 32 + (i & 7)];
    }

    for (int ch = 0; ch < 4; ++ch) {
        // split+store current chunk
        #pragma unroll
        for (int u = 0; u < 2; ++u)
            store_split_A(Ash, Asl, tid + u * 256, pa[u]);
        #pragma unroll
        for (int u = 0; u < 4; ++u)
            store_split_A(Bsh, Bsl, tid + u * 256, pb[u]);
        __syncthreads();

        // prefetch next chunk (overlaps with mma below)
        if (ch < 3) {
            #pragma unroll
            for (int u = 0; u < 2; ++u) {
                const int i = tid + u * 256;
                const int gr = row0 + (i >> 3);
                pa[u] = (gr < rows) ? h4[gr * 32 + (ch + 1) * 8 + (i & 7)]
                                    : make_float4(0.f, 0.f, 0.f, 0.f);
            }
            #pragma unroll
            for (int u = 0; u < 4; ++u) {
                const int i = tid + u * 256;
                pb[u] = W4[(i >> 3) * 32 + (ch + 1) * 8 + (i & 7)];
            }
        }

        mma_chunk(Ash, Asl, Bsh, Bsl, m0, n0, g, q, c);
        __syncthreads();
    }

    // epilogue
    #pragma unroll
    for (int mt = 0; mt < 2; ++mt) {
        const int rlo = row0 + m0 + mt * 16 + g;
        const int rhi = rlo + 8;
        #pragma unroll
        for (int nt = 0; nt < 4; ++nt) {
            const int col = n0 + nt * 8 + q * 2;
            if (rlo < rows)
                *(float2*)&m[rlo * DD + col] = make_float2(c[mt][nt][0], c[mt][nt][1]);
            if (rhi < rows)
                *(float2*)&m[rhi * DD + col] = make_float2(c[mt][nt][2], c[mt][nt][3]);
        }
    }
}

// ============================================================================
// Kernel 2: CSR gather. One warp per target node, both batches, no atomics.
// ============================================================================
__global__ __launch_bounds__(256) void gather_csr(
    const float* __restrict__ m, const float* __restrict__ rel_emb,
    const int* __restrict__ base, const int* __restrict__ sorted,
    float* __restrict__ agg, int N, int ND)
{
    const int nid = blockIdx.x * 8 + (threadIdx.x >> 5);
    if (nid >= N) return;
    const int lane = threadIdx.x & 31;

    const int start = (nid == 0) ? 0 : __ldg(&base[nid - 1]);
    const int end = __ldg(&base[nid]);

    const float4* m4 = (const float4*)m;
    const float4* r4 = (const float4*)rel_emb;
    const int ND4 = ND / 4;

    float4 a0 = make_float4(0.f,0.f,0.f,0.f);
    float4 a1 = make_float4(0.f,0.f,0.f,0.f);

    int i = start;
    for (; i + 1 < end; i += 2) {
        const int pA = __ldg(&sorted[i]);
        const int pB = __ldg(&sorted[i + 1]);
        const int sA = pA & 0x1FFFF, rA = pA >> 17;
        const int sB = pB & 0x1FFFF, rB = pB >> 17;
        const float4 rvA = r4[rA * 32 + lane];
        const float4 m0A = m4[sA * 32 + lane];
        const float4 m1A = m4[ND4 + sA * 32 + lane];
        const float4 rvB = r4[rB * 32 + lane];
        const float4 m0B = m4[sB * 32 + lane];
        const float4 m1B = m4[ND4 + sB * 32 + lane];
        a0.x = fmaf(m0A.x, rvA.x, a0.x); a0.y = fmaf(m0A.y, rvA.y, a0.y);
        a0.z = fmaf(m0A.z, rvA.z, a0.z); a0.w = fmaf(m0A.w, rvA.w, a0.w);
        a1.x = fmaf(m1A.x, rvA.x, a1.x); a1.y = fmaf(m1A.y, rvA.y, a1.y);
        a1.z = fmaf(m1A.z, rvA.z, a1.z); a1.w = fmaf(m1A.w, rvA.w, a1.w);
        a0.x = fmaf(m0B.x, rvB.x, a0.x); a0.y = fmaf(m0B.y, rvB.y, a0.y);
        a0.z = fmaf(m0B.z, rvB.z, a0.z); a0.w = fmaf(m0B.w, rvB.w, a0.w);
        a1.x = fmaf(m1B.x, rvB.x, a1.x); a1.y = fmaf(m1B.y, rvB.y, a1.y);
        a1.z = fmaf(m1B.z, rvB.z, a1.z); a1.w = fmaf(m1B.w, rvB.w, a1.w);
    }
    if (i < end) {
        const int p = __ldg(&sorted[i]);
        const int s = p & 0x1FFFF, r = p >> 17;
        const float4 rv = r4[r * 32 + lane];
        const float4 m0 = m4[s * 32 + lane];
        const float4 m1 = m4[ND4 + s * 32 + lane];
        a0.x = fmaf(m0.x, rv.x, a0.x); a0.y = fmaf(m0.y, rv.y, a0.y);
        a0.z = fmaf(m0.z, rv.z, a0.z); a0.w = fmaf(m0.w, rv.w, a0.w);
        a1.x = fmaf(m1.x, rv.x, a1.x); a1.y = fmaf(m1.y, rv.y, a1.y);
        a1.z = fmaf(m1.z, rv.z, a1.z); a1.w = fmaf(m1.w, rv.w, a1.w);
    }

    float4* agg4 = (float4*)agg;
    agg4[nid * 32 + lane] = a0;
    agg4[ND4 + nid * 32 + lane] = a1;
}

// ============================================================================
// Kernel 3: upd = relu([h|agg] @ W_upd^T + b); out = LN(h + upd)
// tf32x3, R5 config + register-prefetch pipeline; K=256 (8 chunks)
// ============================================================================
__global__ __launch_bounds__(256) void update_ln_mma(
    const float* __restrict__ h, const float* __restrict__ agg,
    const float* __restrict__ Wupd, const float* __restrict__ bupd,
    const float* __restrict__ lns, const float* __restrict__ lnb,
    float* __restrict__ out, int rows)
{
    extern __shared__ float sm[];
    float* Ash = sm + OF_ASH;
    float* Asl = sm + OF_ASL;
    float* Bsh = sm + OF_BSH;
    float* Bsl = sm + OF_BSL;

    const int tid = threadIdx.x;
    const int lane = tid & 31, wid = tid >> 5;
    const int g = lane >> 2, q = lane & 3;
    const int m0 = (wid >> 2) * 32, n0 = (wid & 3) * 32;
    const int warp_n = wid & 3;
    const int row0 = blockIdx.x * 64;

    const float4* h4 = (const float4*)h;
    const float4* a4 = (const float4*)agg;
    const float4* W4 = (const float4*)Wupd;    // row stride 64 float4

    float c[2][4][4];
    #pragma unroll
    for (int mt = 0; mt < 2; ++mt)
        #pragma unroll
        for (int nt = 0; nt < 4; ++nt)
            #pragma unroll
            for (int k = 0; k < 4; ++k) c[mt][nt][k] = 0.f;

    float4 pa[2], pb[4];
    // prefetch chunk 0 (h columns 0..31)
    #pragma unroll
    for (int u = 0; u < 2; ++u) {
        const int i = tid + u * 256;
        const int gr = row0 + (i >> 3);
        pa[u] = (gr < rows) ? h4[gr * 32 + (i & 7)]
                            : make_float4(0.f, 0.f, 0.f, 0.f);
    }
    #pragma unroll
    for (int u = 0; u < 4; ++u) {
        const int i = tid + u * 256;
        pb[u] = W4[(i >> 3) * 64 + (i & 7)];
    }

    for (int ch = 0; ch < 8; ++ch) {
        #pragma unroll
        for (int u = 0; u < 2; ++u)
            store_split_A(Ash, Asl, tid + u * 256, pa[u]);
        #pragma unroll
        for (int u = 0; u < 4; ++u)
            store_split_A(Bsh, Bsl, tid + u * 256, pb[u]);
        __syncthreads();

        if (ch < 7) {
            const int nc = ch + 1;
            const float4* src4 = (nc < 4) ? h4 : a4;
            const int scol8 = (nc & 3) * 8;
            #pragma unroll
            for (int u = 0; u < 2; ++u) {
                const int i = tid + u * 256;
                const int gr = row0 + (i >> 3);
                pa[u] = (gr < rows) ? src4[gr * 32 + scol8 + (i & 7)]
                                    : make_float4(0.f, 0.f, 0.f, 0.f);
            }
            #pragma unroll
            for (int u = 0; u < 4; ++u) {
                const int i = tid + u * 256;
                pb[u] = W4[(i >> 3) * 64 + nc * 8 + (i & 7)];
            }
        }

        mma_chunk(Ash, Asl, Bsh, Bsl, m0, n0, g, q, c);
        __syncthreads();
    }

    // ---- epilogue: v = relu(C + b) + h, LN across row ----
    float2* red = (float2*)sm;          // red[row(64)][warp_n(4)]

    float2 bias[4], lsc[4], lbi[4];
    #pragma unroll
    for (int nt = 0; nt < 4; ++nt) {
        const int col = n0 + nt * 8 + q * 2;
        bias[nt] = *(const float2*)&bupd[col];
        lsc[nt]  = *(const float2*)&lns[col];
        lbi[nt]  = *(const float2*)&lnb[col];
    }

    float s1v[2][2], s2v[2][2];
    #pragma unroll
    for (int mt = 0; mt < 2; ++mt) {
        const int rlo = row0 + m0 + mt * 16 + g;
        const int rhi = rlo + 8;
        float p1lo = 0.f, p2lo = 0.f, p1hi = 0.f, p2hi = 0.f;
        #pragma unroll
        for (int nt = 0; nt < 4; ++nt) {
            const int col = n0 + nt * 8 + q * 2;
            float2 hlo = (rlo < rows) ? *(const float2*)&h[rlo * DD + col]
                                      : make_float2(0.f, 0.f);
            float2 hhi = (rhi < rows) ? *(const float2*)&h[rhi * DD + col]
                                      : make_float2(0.f, 0.f);
            float v0 = fmaxf(c[mt][nt][0] + bias[nt].x, 0.f) + hlo.x;
            float v1 = fmaxf(c[mt][nt][1] + bias[nt].y, 0.f) + hlo.y;
            float v2 = fmaxf(c[mt][nt][2] + bias[nt].x, 0.f) + hhi.x;
            float v3 = fmaxf(c[mt][nt][3] + bias[nt].y, 0.f) + hhi.y;
            c[mt][nt][0] = v0; c[mt][nt][1] = v1;
            c[mt][nt][2] = v2; c[mt][nt][3] = v3;
            p1lo += v0 + v1;  p2lo += v0*v0 + v1*v1;
            p1hi += v2 + v3;  p2hi += v2*v2 + v3*v3;
        }
        s1v[mt][0] = p1lo; s2v[mt][0] = p2lo;
        s1v[mt][1] = p1hi; s2v[mt][1] = p2hi;
    }
    #pragma unroll
    for (int mt = 0; mt < 2; ++mt)
        #pragma unroll
        for (int hf = 0; hf < 2; ++hf) {
            float s1 = s1v[mt][hf], s2 = s2v[mt][hf];
            s1 += __shfl_xor_sync(0xffffffffu, s1, 1);
            s2 += __shfl_xor_sync(0xffffffffu, s2, 1);
            s1 += __shfl_xor_sync(0xffffffffu, s1, 2);
            s2 += __shfl_xor_sync(0xffffffffu, s2, 2);
            if (q == 0) {
                const int rl = m0 + mt * 16 + hf * 8 + g;
                red[rl * 4 + warp_n] = make_float2(s1, s2);
            }
        }
    __syncthreads();

    #pragma unroll
    for (int mt = 0; mt < 2; ++mt) {
        #pragma unroll
        for (int hf = 0; hf < 2; ++hf) {
            const int rl = m0 + mt * 16 + hf * 8 + g;
            const int gr = row0 + rl;
            float S1 = 0.f, S2 = 0.f;
            #pragma unroll
            for (int w = 0; w < 4; ++w) {
                float2 p = red[rl * 4 + w];
                S1 += p.x; S2 += p.y;
            }
            const float mu  = S1 * (1.f / 128.f);
            const float var = S2 * (1.f / 128.f) - mu * mu;
            const float rs  = rsqrtf(var + 1e-5f);
            if (gr < rows) {
                #pragma unroll
                for (int nt = 0; nt < 4; ++nt) {
                    const int col = n0 + nt * 8 + q * 2;
                    const float v0 = c[mt][nt][hf * 2 + 0];
                    const float v1 = c[mt][nt][hf * 2 + 1];
                    float2 o;
                    o.x = (v0 - mu) * rs * lsc[nt].x + lbi[nt].x;
                    o.y = (v1 - mu) * rs * lsc[nt].y + lbi[nt].y;
                    *(float2*)&out[gr * DD + col] = o;
                }
            }
        }
    }
}

// ============================================================================
// host
// ============================================================================
extern "C" void kernel_launch(void* const* d_in, const int* in_sizes, int n_in,
                              void* d_out, int out_size)
{
    const float* h    = (const float*)d_in[0];
    const float* Wmsg = (const float*)d_in[1];
    const float* rel  = (const float*)d_in[2];
    const float* Wupd = (const float*)d_in[3];
    const float* bupd = (const float*)d_in[4];
    const float* lns  = (const float*)d_in[5];
    const float* lnb  = (const float*)d_in[6];
    const int*   esrc = (const int*)d_in[7];
    const int*   etgt = (const int*)d_in[8];
    const int*   erel = (const int*)d_in[9];
    float* out = (float*)d_out;

    const int E    = in_sizes[7];
    const int rows = in_sizes[0] / DD;     // B*N
    const int N    = rows / 2;
    const int ND   = N * DD;
    const int tiles = (rows + 63) / 64;

    void *pm, *pa, *pc, *pb, *ps;
    cudaGetSymbolAddress(&pm, g_m);
    cudaGetSymbolAddress(&pa, g_agg);
    cudaGetSymbolAddress(&pc, g_cnt);
    cudaGetSymbolAddress(&pb, g_base);
    cudaGetSymbolAddress(&ps, g_sorted);
    float* d_m    = (float*)pm;
    float* d_agg  = (float*)pa;
    int*   d_cnt  = (int*)pc;
    int*   d_base = (int*)pb;
    int*   d_sort = (int*)ps;

    cudaFuncSetAttribute(msg_gemm_mma,
        cudaFuncAttributeMaxDynamicSharedMemorySize, SM_BYTES);
    cudaFuncSetAttribute(update_ln_mma,
        cudaFuncAttributeMaxDynamicSharedMemorySize, SM_BYTES);

    // edge sort (counting sort by target)
    cudaMemsetAsync(d_cnt, 0, (size_t)N * sizeof(int), 0);
    hist_k<<<(E + 255) / 256, 256>>>(etgt, d_cnt, E);
    exscan_k<<<1, 1024>>>(d_cnt, d_base, N);
    fill_k<<<(E + 255) / 256, 256>>>(esrc, etgt, erel, d_base, d_sort, E);

    // m = h @ W_msg^T
    msg_gemm_mma<<<tiles, 256, SM_BYTES>>>(h, Wmsg, d_m, rows);

    // agg[t] = sum_{e: tgt=t} m[src_e] * rel_emb[rel_e]
    gather_csr<<<(N + 7) / 8, 256>>>(d_m, rel, d_base, d_sort, d_agg, N, ND);

    // update + residual + layernorm
    update_ln_mma<<<tiles, 256, SM_BYTES>>>(h, d_agg, Wupd, bupd, lns, lnb, out, rows);
}

// round 10
// speedup vs baseline: 1.4652x; 1.2555x over previous
#include <cuda_runtime.h>
#include <cuda_bf16.h>
#include <cstdint>

#define DD 128
#define MAXROWS (2*50000)
#define MAXN 50001
#define MAXE 800000

// scratch (__device__ globals — allocation-free rule)
__device__ float g_m[MAXROWS * DD];
__device__ float g_agg[MAXROWS * DD];
__device__ int   g_cnt[MAXN];
__device__ int   g_base[MAXN];
__device__ int   g_sorted[MAXE];

// ---------------------------------------------------------------------------
// helpers
// ---------------------------------------------------------------------------
// split a pair of fp32 (consecutive k) into packed bf16x2 hi and lo words
__device__ __forceinline__ void split_bf16_pair(float x, float y,
                                                uint32_t& hi, uint32_t& lo)
{
    __nv_bfloat16 hx = __float2bfloat16(x);
    __nv_bfloat16 hy = __float2bfloat16(y);
    float rx = x - __bfloat162float(hx);
    float ry = y - __bfloat162float(hy);
    __nv_bfloat16 lx = __float2bfloat16(rx);
    __nv_bfloat16 ly = __float2bfloat16(ry);
    __nv_bfloat162 hp(hx, hy);   // .x = low half (k even), .y = high (k odd)
    __nv_bfloat162 lp(lx, ly);
    hi = *reinterpret_cast<uint32_t*>(&hp);
    lo = *reinterpret_cast<uint32_t*>(&lp);
}

__device__ __forceinline__ void mma_bf16(float* c, const uint32_t* a,
                                         const uint32_t* b)
{
    asm volatile(
        "mma.sync.aligned.m16n8k16.row.col.f32.bf16.bf16.f32 "
        "{%0,%1,%2,%3}, {%4,%5,%6,%7}, {%8,%9}, {%0,%1,%2,%3};"
        : "+f"(c[0]), "+f"(c[1]), "+f"(c[2]), "+f"(c[3])
        : "r"(a[0]), "r"(a[1]), "r"(a[2]), "r"(a[3]),
          "r"(b[0]), "r"(b[1]));
}

// smem layout (uint32 = bf16x2 pair units), stride 20 -> conflict-free
// (g*20+q mod 32 distinct for g 0..7, q 0..3)
#define SB_STR 20
#define OF_ASH 0
#define OF_ASL (64 * SB_STR)
#define OF_BSH (2 * 64 * SB_STR)
#define OF_BSL (OF_BSH + 128 * SB_STR)
#define SM_U32 (OF_BSL + 128 * SB_STR)
#define SM_BYTES (SM_U32 * 4)          // 30720

// ============================================================================
// Edge sort (counting sort by target)
// ============================================================================
__global__ __launch_bounds__(256) void hist_k(const int* __restrict__ etgt,
                                              int* __restrict__ cnt, int E)
{
    int e = blockIdx.x * blockDim.x + threadIdx.x;
    if (e < E) atomicAdd(&cnt[etgt[e]], 1);
}

__global__ __launch_bounds__(1024) void exscan_k(const int* __restrict__ cnt,
                                                 int* __restrict__ base, int n)
{
    __shared__ int ws[32];
    __shared__ int carry_s;
    const int tid = threadIdx.x;
    const int lane = tid & 31, wid = tid >> 5;
    if (tid == 0) carry_s = 0;
    __syncthreads();

    for (int chunk = 0; chunk < n; chunk += 1024) {
        const int i = chunk + tid;
        const int x = (i < n) ? cnt[i] : 0;
        int v = x;
        #pragma unroll
        for (int o = 1; o < 32; o <<= 1) {
            int t = __shfl_up_sync(0xffffffffu, v, o);
            if (lane >= o) v += t;
        }
        if (lane == 31) ws[wid] = v;
        __syncthreads();
        if (wid == 0) {
            int w = ws[lane];
            #pragma unroll
            for (int o = 1; o < 32; o <<= 1) {
                int t = __shfl_up_sync(0xffffffffu, w, o);
                if (lane >= o) w += t;
            }
            ws[lane] = w;
        }
        __syncthreads();
        const int woff = (wid > 0) ? ws[wid - 1] : 0;
        const int carry = carry_s;
        const int incl = v + woff + carry;
        if (i < n) base[i] = incl - x;
        __syncthreads();
        if (tid == 1023) carry_s = incl;
        __syncthreads();
    }
}

__global__ __launch_bounds__(256) void fill_k(
    const int* __restrict__ esrc, const int* __restrict__ etgt,
    const int* __restrict__ erel, int* __restrict__ base,
    int* __restrict__ sorted, int E)
{
    int e = blockIdx.x * blockDim.x + threadIdx.x;
    if (e >= E) return;
    const int t = etgt[e];
    const int pos = atomicAdd(&base[t], 1);
    sorted[pos] = esrc[e] | (erel[e] << 17);
}

// ---------------------------------------------------------------------------
// staging: thread i covers row r=i>>3, float4 j4=i&7 (k = j4*4..j4*4+3)
// -> bf16x2 pairs at indices j4*2, j4*2+1
// ---------------------------------------------------------------------------
__device__ __forceinline__ void stage_split(uint32_t* Sh, uint32_t* Sl,
                                            int i, float4 v)
{
    const int r = i >> 3, j4 = i & 7;
    uint32_t h0, l0, h1, l1;
    split_bf16_pair(v.x, v.y, h0, l0);
    split_bf16_pair(v.z, v.w, h1, l1);
    uint2 hh = make_uint2(h0, h1);
    uint2 ll = make_uint2(l0, l1);
    *(uint2*)&Sh[r * SB_STR + j4 * 2] = hh;
    *(uint2*)&Sl[r * SB_STR + j4 * 2] = ll;
}

// ---------------------------------------------------------------------------
// mma over one staged K=32 chunk (2 k16 steps); warp tile 32x32
// ---------------------------------------------------------------------------
__device__ __forceinline__ void mma_chunk(const uint32_t* Ash, const uint32_t* Asl,
                                          const uint32_t* Bsh, const uint32_t* Bsl,
                                          int m0, int n0, int g, int q,
                                          float c[2][4][4])
{
    #pragma unroll
    for (int ks = 0; ks < 2; ++ks) {
        const int kp = ks * 8;                 // pair offset within row
        uint32_t ah[2][4], al[2][4], bh[4][2], bl[4][2];
        #pragma unroll
        for (int mt = 0; mt < 2; ++mt) {
            const int r0i = (m0 + mt * 16 + g) * SB_STR + kp + q;
            const int r1i = r0i + 8 * SB_STR;
            ah[mt][0] = Ash[r0i];
            ah[mt][1] = Ash[r1i];
            ah[mt][2] = Ash[r0i + 4];
            ah[mt][3] = Ash[r1i + 4];
            al[mt][0] = Asl[r0i];
            al[mt][1] = Asl[r1i];
            al[mt][2] = Asl[r0i + 4];
            al[mt][3] = Asl[r1i + 4];
        }
        #pragma unroll
        for (int nt = 0; nt < 4; ++nt) {
            const int rb = (n0 + nt * 8 + g) * SB_STR + kp + q;
            bh[nt][0] = Bsh[rb];
            bh[nt][1] = Bsh[rb + 4];
            bl[nt][0] = Bsl[rb];
            bl[nt][1] = Bsl[rb + 4];
        }
        #pragma unroll
        for (int mt = 0; mt < 2; ++mt)
            #pragma unroll
            for (int nt = 0; nt < 4; ++nt) {
                mma_bf16(c[mt][nt], ah[mt], bh[nt]);
                mma_bf16(c[mt][nt], ah[mt], bl[nt]);
                mma_bf16(c[mt][nt], al[mt], bh[nt]);
            }
    }
}

// ============================================================================
// Kernel 1: m = h @ W_msg^T  (bf16x3, 64-row tile, R5 structure)
// ============================================================================
__global__ __launch_bounds__(256) void msg_gemm_mma(
    const float* __restrict__ h, const float* __restrict__ W,
    float* __restrict__ m, int rows)
{
    extern __shared__ uint32_t sm[];
    uint32_t* Ash = sm + OF_ASH;
    uint32_t* Asl = sm + OF_ASL;
    uint32_t* Bsh = sm + OF_BSH;
    uint32_t* Bsl = sm + OF_BSL;

    const int tid = threadIdx.x;
    const int lane = tid & 31, wid = tid >> 5;
    const int g = lane >> 2, q = lane & 3;
    const int m0 = (wid >> 2) * 32, n0 = (wid & 3) * 32;
    const int row0 = blockIdx.x * 64;

    const float4* h4 = (const float4*)h;
    const float4* W4 = (const float4*)W;

    float c[2][4][4];
    #pragma unroll
    for (int mt = 0; mt < 2; ++mt)
        #pragma unroll
        for (int nt = 0; nt < 4; ++nt)
            #pragma unroll
            for (int k = 0; k < 4; ++k) c[mt][nt][k] = 0.f;

    for (int ch = 0; ch < 4; ++ch) {
        // stage A (64 x 32)
        #pragma unroll
        for (int u = 0; u < 2; ++u) {
            const int i = tid + u * 256;
            const int gr = row0 + (i >> 3);
            float4 v = (gr < rows) ? h4[gr * 32 + ch * 8 + (i & 7)]
                                   : make_float4(0.f, 0.f, 0.f, 0.f);
            stage_split(Ash, Asl, i, v);
        }
        // stage B (128 x 32)
        #pragma unroll
        for (int u = 0; u < 4; ++u) {
            const int i = tid + u * 256;
            float4 w = W4[(i >> 3) * 32 + ch * 8 + (i & 7)];
            stage_split(Bsh, Bsl, i, w);
        }
        __syncthreads();
        mma_chunk(Ash, Asl, Bsh, Bsl, m0, n0, g, q, c);
        __syncthreads();
    }

    // epilogue
    #pragma unroll
    for (int mt = 0; mt < 2; ++mt) {
        const int rlo = row0 + m0 + mt * 16 + g;
        const int rhi = rlo + 8;
        #pragma unroll
        for (int nt = 0; nt < 4; ++nt) {
            const int col = n0 + nt * 8 + q * 2;
            if (rlo < rows)
                *(float2*)&m[rlo * DD + col] = make_float2(c[mt][nt][0], c[mt][nt][1]);
            if (rhi < rows)
                *(float2*)&m[rhi * DD + col] = make_float2(c[mt][nt][2], c[mt][nt][3]);
        }
    }
}

// ============================================================================
// Kernel 2: CSR gather. One warp per target node, both batches, no atomics.
// ============================================================================
__global__ __launch_bounds__(256) void gather_csr(
    const float* __restrict__ m, const float* __restrict__ rel_emb,
    const int* __restrict__ base, const int* __restrict__ sorted,
    float* __restrict__ agg, int N, int ND)
{
    const int nid = blockIdx.x * 8 + (threadIdx.x >> 5);
    if (nid >= N) return;
    const int lane = threadIdx.x & 31;

    const int start = (nid == 0) ? 0 : __ldg(&base[nid - 1]);
    const int end = __ldg(&base[nid]);

    const float4* m4 = (const float4*)m;
    const float4* r4 = (const float4*)rel_emb;
    const int ND4 = ND / 4;

    float4 a0 = make_float4(0.f,0.f,0.f,0.f);
    float4 a1 = make_float4(0.f,0.f,0.f,0.f);

    int i = start;
    for (; i + 1 < end; i += 2) {
        const int pA = __ldg(&sorted[i]);
        const int pB = __ldg(&sorted[i + 1]);
        const int sA = pA & 0x1FFFF, rA = pA >> 17;
        const int sB = pB & 0x1FFFF, rB = pB >> 17;
        const float4 rvA = r4[rA * 32 + lane];
        const float4 m0A = m4[sA * 32 + lane];
        const float4 m1A = m4[ND4 + sA * 32 + lane];
        const float4 rvB = r4[rB * 32 + lane];
        const float4 m0B = m4[sB * 32 + lane];
        const float4 m1B = m4[ND4 + sB * 32 + lane];
        a0.x = fmaf(m0A.x, rvA.x, a0.x); a0.y = fmaf(m0A.y, rvA.y, a0.y);
        a0.z = fmaf(m0A.z, rvA.z, a0.z); a0.w = fmaf(m0A.w, rvA.w, a0.w);
        a1.x = fmaf(m1A.x, rvA.x, a1.x); a1.y = fmaf(m1A.y, rvA.y, a1.y);
        a1.z = fmaf(m1A.z, rvA.z, a1.z); a1.w = fmaf(m1A.w, rvA.w, a1.w);
        a0.x = fmaf(m0B.x, rvB.x, a0.x); a0.y = fmaf(m0B.y, rvB.y, a0.y);
        a0.z = fmaf(m0B.z, rvB.z, a0.z); a0.w = fmaf(m0B.w, rvB.w, a0.w);
        a1.x = fmaf(m1B.x, rvB.x, a1.x); a1.y = fmaf(m1B.y, rvB.y, a1.y);
        a1.z = fmaf(m1B.z, rvB.z, a1.z); a1.w = fmaf(m1B.w, rvB.w, a1.w);
    }
    if (i < end) {
        const int p = __ldg(&sorted[i]);
        const int s = p & 0x1FFFF, r = p >> 17;
        const float4 rv = r4[r * 32 + lane];
        const float4 m0 = m4[s * 32 + lane];
        const float4 m1 = m4[ND4 + s * 32 + lane];
        a0.x = fmaf(m0.x, rv.x, a0.x); a0.y = fmaf(m0.y, rv.y, a0.y);
        a0.z = fmaf(m0.z, rv.z, a0.z); a0.w = fmaf(m0.w, rv.w, a0.w);
        a1.x = fmaf(m1.x, rv.x, a1.x); a1.y = fmaf(m1.y, rv.y, a1.y);
        a1.z = fmaf(m1.z, rv.z, a1.z); a1.w = fmaf(m1.w, rv.w, a1.w);
    }

    float4* agg4 = (float4*)agg;
    agg4[nid * 32 + lane] = a0;
    agg4[ND4 + nid * 32 + lane] = a1;
}

// ============================================================================
// Kernel 3: upd = relu([h|agg] @ W_upd^T + b); out = LN(h + upd)
// bf16x3, R5 structure; K=256 in 8 chunks (0-3: h, 4-7: agg)
// ============================================================================
__global__ __launch_bounds__(256) void update_ln_mma(
    const float* __restrict__ h, const float* __restrict__ agg,
    const float* __restrict__ Wupd, const float* __restrict__ bupd,
    const float* __restrict__ lns, const float* __restrict__ lnb,
    float* __restrict__ out, int rows)
{
    extern __shared__ uint32_t sm[];
    uint32_t* Ash = sm + OF_ASH;
    uint32_t* Asl = sm + OF_ASL;
    uint32_t* Bsh = sm + OF_BSH;
    uint32_t* Bsl = sm + OF_BSL;

    const int tid = threadIdx.x;
    const int lane = tid & 31, wid = tid >> 5;
    const int g = lane >> 2, q = lane & 3;
    const int m0 = (wid >> 2) * 32, n0 = (wid & 3) * 32;
    const int warp_n = wid & 3;
    const int row0 = blockIdx.x * 64;

    const float4* h4 = (const float4*)h;
    const float4* a4 = (const float4*)agg;
    const float4* W4 = (const float4*)Wupd;    // row stride 64 float4

    float c[2][4][4];
    #pragma unroll
    for (int mt = 0; mt < 2; ++mt)
        #pragma unroll
        for (int nt = 0; nt < 4; ++nt)
            #pragma unroll
            for (int k = 0; k < 4; ++k) c[mt][nt][k] = 0.f;

    for (int ch = 0; ch < 8; ++ch) {
        const float4* src4 = (ch < 4) ? h4 : a4;
        const int scol8 = (ch & 3) * 8;
        #pragma unroll
        for (int u = 0; u < 2; ++u) {
            const int i = tid + u * 256;
            const int gr = row0 + (i >> 3);
            float4 v = (gr < rows) ? src4[gr * 32 + scol8 + (i & 7)]
                                   : make_float4(0.f, 0.f, 0.f, 0.f);
            stage_split(Ash, Asl, i, v);
        }
        #pragma unroll
        for (int u = 0; u < 4; ++u) {
            const int i = tid + u * 256;
            float4 w = W4[(i >> 3) * 64 + ch * 8 + (i & 7)];
            stage_split(Bsh, Bsl, i, w);
        }
        __syncthreads();
        mma_chunk(Ash, Asl, Bsh, Bsl, m0, n0, g, q, c);
        __syncthreads();
    }

    // ---- epilogue: v = relu(C + b) + h, LN across row ----
    float2* red = (float2*)sm;          // red[row(64)][warp_n(4)]

    float2 bias[4], lsc[4], lbi[4];
    #pragma unroll
    for (int nt = 0; nt < 4; ++nt) {
        const int col = n0 + nt * 8 + q * 2;
        bias[nt] = *(const float2*)&bupd[col];
        lsc[nt]  = *(const float2*)&lns[col];
        lbi[nt]  = *(const float2*)&lnb[col];
    }

    float s1v[2][2], s2v[2][2];
    #pragma unroll
    for (int mt = 0; mt < 2; ++mt) {
        const int rlo = row0 + m0 + mt * 16 + g;
        const int rhi = rlo + 8;
        float p1lo = 0.f, p2lo = 0.f, p1hi = 0.f, p2hi = 0.f;
        #pragma unroll
        for (int nt = 0; nt < 4; ++nt) {
            const int col = n0 + nt * 8 + q * 2;
            float2 hlo = (rlo < rows) ? *(const float2*)&h[rlo * DD + col]
                                      : make_float2(0.f, 0.f);
            float2 hhi = (rhi < rows) ? *(const float2*)&h[rhi * DD + col]
                                      : make_float2(0.f, 0.f);
            float v0 = fmaxf(c[mt][nt][0] + bias[nt].x, 0.f) + hlo.x;
            float v1 = fmaxf(c[mt][nt][1] + bias[nt].y, 0.f) + hlo.y;
            float v2 = fmaxf(c[mt][nt][2] + bias[nt].x, 0.f) + hhi.x;
            float v3 = fmaxf(c[mt][nt][3] + bias[nt].y, 0.f) + hhi.y;
            c[mt][nt][0] = v0; c[mt][nt][1] = v1;
            c[mt][nt][2] = v2; c[mt][nt][3] = v3;
            p1lo += v0 + v1;  p2lo += v0*v0 + v1*v1;
            p1hi += v2 + v3;  p2hi += v2*v2 + v3*v3;
        }
        s1v[mt][0] = p1lo; s2v[mt][0] = p2lo;
        s1v[mt][1] = p1hi; s2v[mt][1] = p2hi;
    }
    #pragma unroll
    for (int mt = 0; mt < 2; ++mt)
        #pragma unroll
        for (int hf = 0; hf < 2; ++hf) {
            float s1 = s1v[mt][hf], s2 = s2v[mt][hf];
            s1 += __shfl_xor_sync(0xffffffffu, s1, 1);
            s2 += __shfl_xor_sync(0xffffffffu, s2, 1);
            s1 += __shfl_xor_sync(0xffffffffu, s1, 2);
            s2 += __shfl_xor_sync(0xffffffffu, s2, 2);
            if (q == 0) {
                const int rl = m0 + mt * 16 + hf * 8 + g;
                red[rl * 4 + warp_n] = make_float2(s1, s2);
            }
        }
    __syncthreads();

    #pragma unroll
    for (int mt = 0; mt < 2; ++mt) {
        #pragma unroll
        for (int hf = 0; hf < 2; ++hf) {
            const int rl = m0 + mt * 16 + hf * 8 + g;
            const int gr = row0 + rl;
            float S1 = 0.f, S2 = 0.f;
            #pragma unroll
            for (int w = 0; w < 4; ++w) {
                float2 p = red[rl * 4 + w];
                S1 += p.x; S2 += p.y;
            }
            const float mu  = S1 * (1.f / 128.f);
            const float var = S2 * (1.f / 128.f) - mu * mu;
            const float rs  = rsqrtf(var + 1e-5f);
            if (gr < rows) {
                #pragma unroll
                for (int nt = 0; nt < 4; ++nt) {
                    const int col = n0 + nt * 8 + q * 2;
                    const float v0 = c[mt][nt][hf * 2 + 0];
                    const float v1 = c[mt][nt][hf * 2 + 1];
                    float2 o;
                    o.x = (v0 - mu) * rs * lsc[nt].x + lbi[nt].x;
                    o.y = (v1 - mu) * rs * lsc[nt].y + lbi[nt].y;
                    *(float2*)&out[gr * DD + col] = o;
                }
            }
        }
    }
}

// ============================================================================
// host
// ============================================================================
extern "C" void kernel_launch(void* const* d_in, const int* in_sizes, int n_in,
                              void* d_out, int out_size)
{
    const float* h    = (const float*)d_in[0];
    const float* Wmsg = (const float*)d_in[1];
    const float* rel  = (const float*)d_in[2];
    const float* Wupd = (const float*)d_in[3];
    const float* bupd = (const float*)d_in[4];
    const float* lns  = (const float*)d_in[5];
    const float* lnb  = (const float*)d_in[6];
    const int*   esrc = (const int*)d_in[7];
    const int*   etgt = (const int*)d_in[8];
    const int*   erel = (const int*)d_in[9];
    float* out = (float*)d_out;

    const int E    = in_sizes[7];
    const int rows = in_sizes[0] / DD;     // B*N
    const int N    = rows / 2;
    const int ND   = N * DD;
    const int tiles = (rows + 63) / 64;

    void *pm, *pa, *pc, *pb, *ps;
    cudaGetSymbolAddress(&pm, g_m);
    cudaGetSymbolAddress(&pa, g_agg);
    cudaGetSymbolAddress(&pc, g_cnt);
    cudaGetSymbolAddress(&pb, g_base);
    cudaGetSymbolAddress(&ps, g_sorted);
    float* d_m    = (float*)pm;
    float* d_agg  = (float*)pa;
    int*   d_cnt  = (int*)pc;
    int*   d_base = (int*)pb;
    int*   d_sort = (int*)ps;

    cudaFuncSetAttribute(msg_gemm_mma,
        cudaFuncAttributeMaxDynamicSharedMemorySize, SM_BYTES);
    cudaFuncSetAttribute(update_ln_mma,
        cudaFuncAttributeMaxDynamicSharedMemorySize, SM_BYTES);

    // edge sort (counting sort by target)
    cudaMemsetAsync(d_cnt, 0, (size_t)N * sizeof(int), 0);
    hist_k<<<(E + 255) / 256, 256>>>(etgt, d_cnt, E);
    exscan_k<<<1, 1024>>>(d_cnt, d_base, N);
    fill_k<<<(E + 255) / 256, 256>>>(esrc, etgt, erel, d_base, d_sort, E);

    // m = h @ W_msg^T
    msg_gemm_mma<<<tiles, 256, SM_BYTES>>>(h, Wmsg, d_m, rows);

    // agg[t] = sum_{e: tgt=t} m[src_e] * rel_emb[rel_e]
    gather_csr<<<(N + 7) / 8, 256>>>(d_m, rel, d_base, d_sort, d_agg, N, ND);

    // update + residual + layernorm
    update_ln_mma<<<tiles, 256, SM_BYTES>>>(h, d_agg, Wupd, bupd, lns, lnb, out, rows);
}

// round 11
// speedup vs baseline: 1.4766x; 1.0078x over previous
#include <cuda_runtime.h>
#include <cuda_bf16.h>
#include <cstdint>

#define DD 128
#define MAXROWS (2*50000)
#define MAXN 50001
#define MAXE 800000

// scratch (__device__ globals — allocation-free rule)
__device__ float    g_m[MAXROWS * DD];
__device__ uint32_t g_agg_h[MAXROWS * 64];   // agg packed bf16x2 hi
__device__ uint32_t g_agg_l[MAXROWS * 64];   // agg packed bf16x2 lo
__device__ uint32_t g_Wm_h[8192], g_Wm_l[8192];     // W_msg [128][64 pairs]
__device__ uint32_t g_Wu_h[16384], g_Wu_l[16384];   // W_upd [128][128 pairs]
__device__ int      g_cnt[MAXN];
__device__ int      g_base[MAXN];
__device__ int      g_sorted[MAXE];

// ---------------------------------------------------------------------------
// helpers
// ---------------------------------------------------------------------------
__device__ __forceinline__ void split_bf16_pair(float x, float y,
                                                uint32_t& hi, uint32_t& lo)
{
    __nv_bfloat16 hx = __float2bfloat16(x);
    __nv_bfloat16 hy = __float2bfloat16(y);
    float rx = x - __bfloat162float(hx);
    float ry = y - __bfloat162float(hy);
    __nv_bfloat16 lx = __float2bfloat16(rx);
    __nv_bfloat16 ly = __float2bfloat16(ry);
    __nv_bfloat162 hp(hx, hy);
    __nv_bfloat162 lp(lx, ly);
    hi = *reinterpret_cast<uint32_t*>(&hp);
    lo = *reinterpret_cast<uint32_t*>(&lp);
}

__device__ __forceinline__ void mma_bf16(float* c, const uint32_t* a,
                                         const uint32_t* b)
{
    asm volatile(
        "mma.sync.aligned.m16n8k16.row.col.f32.bf16.bf16.f32 "
        "{%0,%1,%2,%3}, {%4,%5,%6,%7}, {%8,%9}, {%0,%1,%2,%3};"
        : "+f"(c[0]), "+f"(c[1]), "+f"(c[2]), "+f"(c[3])
        : "r"(a[0]), "r"(a[1]), "r"(a[2]), "r"(a[3]),
          "r"(b[0]), "r"(b[1]));
}

// smem layout (uint32 = bf16x2 pair units), stride 20 -> conflict-free
#define SB_STR 20
#define OF_ASH 0
#define OF_ASL (64 * SB_STR)
#define OF_BSH (2 * 64 * SB_STR)
#define OF_BSL (OF_BSH + 128 * SB_STR)
#define SM_U32 (OF_BSL + 128 * SB_STR)
#define SM_BYTES (SM_U32 * 4)          // 30720

// ============================================================================
// Kernel P: pre-split W into packed bf16 hi/lo (row-major pairs, one pass)
// ============================================================================
__global__ __launch_bounds__(256) void presplit_k(
    const float* __restrict__ Wm, const float* __restrict__ Wu,
    uint32_t* __restrict__ wmh, uint32_t* __restrict__ wml,
    uint32_t* __restrict__ wuh, uint32_t* __restrict__ wul)
{
    const int p = blockIdx.x * 256 + threadIdx.x;
    if (p < 8192) {
        float2 v = ((const float2*)Wm)[p];
        uint32_t h, l;
        split_bf16_pair(v.x, v.y, h, l);
        wmh[p] = h; wml[p] = l;
    }
    const int p2 = p - 8192;
    if (p2 >= 0 && p2 < 16384) {
        float2 v = ((const float2*)Wu)[p2];
        uint32_t h, l;
        split_bf16_pair(v.x, v.y, h, l);
        wuh[p2] = h; wul[p2] = l;
    }
}

// ============================================================================
// Edge sort (counting sort by target)
// ============================================================================
__global__ __launch_bounds__(256) void hist_k(const int* __restrict__ etgt,
                                              int* __restrict__ cnt, int E)
{
    int e = blockIdx.x * blockDim.x + threadIdx.x;
    if (e < E) atomicAdd(&cnt[etgt[e]], 1);
}

// single-block exclusive scan, 4 elements per thread (int4)
__global__ __launch_bounds__(1024) void exscan_k(const int* __restrict__ cnt,
                                                 int* __restrict__ base, int n)
{
    __shared__ int ws[32];
    __shared__ int carry_s;
    const int tid = threadIdx.x;
    const int lane = tid & 31, wid = tid >> 5;
    if (tid == 0) carry_s = 0;
    __syncthreads();

    for (int chunk = 0; chunk < n; chunk += 4096) {
        const int i = chunk + tid * 4;
        int4 x = make_int4(0, 0, 0, 0);
        if (i + 3 < n) {
            x = *(const int4*)&cnt[i];
        } else if (i < n) {
            x.x = cnt[i];
            if (i + 1 < n) x.y = cnt[i + 1];
            if (i + 2 < n) x.z = cnt[i + 2];
        }
        const int s = x.x + x.y + x.z + x.w;
        int v = s;
        #pragma unroll
        for (int o = 1; o < 32; o <<= 1) {
            int t = __shfl_up_sync(0xffffffffu, v, o);
            if (lane >= o) v += t;
        }
        if (lane == 31) ws[wid] = v;
        __syncthreads();
        if (wid == 0) {
            int w = ws[lane];
            #pragma unroll
            for (int o = 1; o < 32; o <<= 1) {
                int t = __shfl_up_sync(0xffffffffu, w, o);
                if (lane >= o) w += t;
            }
            ws[lane] = w;
        }
        __syncthreads();
        const int woff = (wid > 0) ? ws[wid - 1] : 0;
        const int carry = carry_s;
        const int incl = v + woff + carry;
        const int e0 = incl - s;
        if (i + 3 < n) {
            int4 o4 = make_int4(e0, e0 + x.x, e0 + x.x + x.y,
                                e0 + x.x + x.y + x.z);
            *(int4*)&base[i] = o4;
        } else if (i < n) {
            base[i] = e0;
            if (i + 1 < n) base[i + 1] = e0 + x.x;
            if (i + 2 < n) base[i + 2] = e0 + x.x + x.y;
        }
        __syncthreads();
        if (tid == 1023) carry_s = incl;
        __syncthreads();
    }
}

__global__ __launch_bounds__(256) void fill_k(
    const int* __restrict__ esrc, const int* __restrict__ etgt,
    const int* __restrict__ erel, int* __restrict__ base,
    int* __restrict__ sorted, int E)
{
    int e = blockIdx.x * blockDim.x + threadIdx.x;
    if (e >= E) return;
    const int t = etgt[e];
    const int pos = atomicAdd(&base[t], 1);
    sorted[pos] = esrc[e] | (erel[e] << 17);
}

// ---------------------------------------------------------------------------
// staging helpers
// ---------------------------------------------------------------------------
__device__ __forceinline__ void stage_split(uint32_t* Sh, uint32_t* Sl,
                                            int i, float4 v)
{
    const int r = i >> 3, j4 = i & 7;
    uint32_t h0, l0, h1, l1;
    split_bf16_pair(v.x, v.y, h0, l0);
    split_bf16_pair(v.z, v.w, h1, l1);
    *(uint2*)&Sh[r * SB_STR + j4 * 2] = make_uint2(h0, h1);
    *(uint2*)&Sl[r * SB_STR + j4 * 2] = make_uint2(l0, l1);
}

__device__ __forceinline__ void stage_copy(uint32_t* Sh, uint32_t* Sl,
                                           int i, uint2 hh, uint2 ll)
{
    const int r = i >> 3, j4 = i & 7;
    *(uint2*)&Sh[r * SB_STR + j4 * 2] = hh;
    *(uint2*)&Sl[r * SB_STR + j4 * 2] = ll;
}

// ---------------------------------------------------------------------------
// mma over one staged K=32 chunk (2 k16 steps); warp tile 32x32
// ---------------------------------------------------------------------------
__device__ __forceinline__ void mma_chunk(const uint32_t* Ash, const uint32_t* Asl,
                                          const uint32_t* Bsh, const uint32_t* Bsl,
                                          int m0, int n0, int g, int q,
                                          float c[2][4][4])
{
    #pragma unroll
    for (int ks = 0; ks < 2; ++ks) {
        const int kp = ks * 8;
        uint32_t ah[2][4], al[2][4], bh[4][2], bl[4][2];
        #pragma unroll
        for (int mt = 0; mt < 2; ++mt) {
            const int r0i = (m0 + mt * 16 + g) * SB_STR + kp + q;
            const int r1i = r0i + 8 * SB_STR;
            ah[mt][0] = Ash[r0i];
            ah[mt][1] = Ash[r1i];
            ah[mt][2] = Ash[r0i + 4];
            ah[mt][3] = Ash[r1i + 4];
            al[mt][0] = Asl[r0i];
            al[mt][1] = Asl[r1i];
            al[mt][2] = Asl[r0i + 4];
            al[mt][3] = Asl[r1i + 4];
        }
        #pragma unroll
        for (int nt = 0; nt < 4; ++nt) {
            const int rb = (n0 + nt * 8 + g) * SB_STR + kp + q;
            bh[nt][0] = Bsh[rb];
            bh[nt][1] = Bsh[rb + 4];
            bl[nt][0] = Bsl[rb];
            bl[nt][1] = Bsl[rb + 4];
        }
        #pragma unroll
        for (int mt = 0; mt < 2; ++mt)
            #pragma unroll
            for (int nt = 0; nt < 4; ++nt) {
                mma_bf16(c[mt][nt], ah[mt], bh[nt]);
                mma_bf16(c[mt][nt], ah[mt], bl[nt]);
                mma_bf16(c[mt][nt], al[mt], bh[nt]);
            }
    }
}

// ============================================================================
// Kernel 1: m = h @ W_msg^T  (bf16x3; prepacked W; 64-row tile)
// ============================================================================
__global__ __launch_bounds__(256) void msg_gemm_mma(
    const float* __restrict__ h,
    const uint32_t* __restrict__ Wh, const uint32_t* __restrict__ Wl,
    float* __restrict__ m, int rows)
{
    extern __shared__ uint32_t sm[];
    uint32_t* Ash = sm + OF_ASH;
    uint32_t* Asl = sm + OF_ASL;
    uint32_t* Bsh = sm + OF_BSH;
    uint32_t* Bsl = sm + OF_BSL;

    const int tid = threadIdx.x;
    const int lane = tid & 31, wid = tid >> 5;
    const int g = lane >> 2, q = lane & 3;
    const int m0 = (wid >> 2) * 32, n0 = (wid & 3) * 32;
    const int row0 = blockIdx.x * 64;

    const float4* h4 = (const float4*)h;

    float c[2][4][4];
    #pragma unroll
    for (int mt = 0; mt < 2; ++mt)
        #pragma unroll
        for (int nt = 0; nt < 4; ++nt)
            #pragma unroll
            for (int k = 0; k < 4; ++k) c[mt][nt][k] = 0.f;

    for (int ch = 0; ch < 4; ++ch) {
        // stage A (64 x 32): split h
        #pragma unroll
        for (int u = 0; u < 2; ++u) {
            const int i = tid + u * 256;
            const int gr = row0 + (i >> 3);
            float4 v = (gr < rows) ? h4[gr * 32 + ch * 8 + (i & 7)]
                                   : make_float4(0.f, 0.f, 0.f, 0.f);
            stage_split(Ash, Asl, i, v);
        }
        // stage B (128 x 32): copy prepacked W pairs
        #pragma unroll
        for (int u = 0; u < 4; ++u) {
            const int i = tid + u * 256;
            const int r = i >> 3, j4 = i & 7;
            const int pidx = r * 64 + ch * 16 + j4 * 2;
            stage_copy(Bsh, Bsl, i,
                       *(const uint2*)&Wh[pidx], *(const uint2*)&Wl[pidx]);
        }
        __syncthreads();
        mma_chunk(Ash, Asl, Bsh, Bsl, m0, n0, g, q, c);
        __syncthreads();
    }

    // epilogue
    #pragma unroll
    for (int mt = 0; mt < 2; ++mt) {
        const int rlo = row0 + m0 + mt * 16 + g;
        const int rhi = rlo + 8;
        #pragma unroll
        for (int nt = 0; nt < 4; ++nt) {
            const int col = n0 + nt * 8 + q * 2;
            if (rlo < rows)
                *(float2*)&m[rlo * DD + col] = make_float2(c[mt][nt][0], c[mt][nt][1]);
            if (rhi < rows)
                *(float2*)&m[rhi * DD + col] = make_float2(c[mt][nt][2], c[mt][nt][3]);
        }
    }
}

// ============================================================================
// Kernel 2: CSR gather -> agg written as packed bf16 hi/lo
// ============================================================================
__global__ __launch_bounds__(256) void gather_csr(
    const float* __restrict__ m, const float* __restrict__ rel_emb,
    const int* __restrict__ base, const int* __restrict__ sorted,
    uint32_t* __restrict__ aggh, uint32_t* __restrict__ aggl,
    int N, int ND)
{
    const int nid = blockIdx.x * 8 + (threadIdx.x >> 5);
    if (nid >= N) return;
    const int lane = threadIdx.x & 31;

    const int start = (nid == 0) ? 0 : __ldg(&base[nid - 1]);
    const int end = __ldg(&base[nid]);

    const float4* m4 = (const float4*)m;
    const float4* r4 = (const float4*)rel_emb;
    const int ND4 = ND / 4;

    float4 a0 = make_float4(0.f,0.f,0.f,0.f);
    float4 a1 = make_float4(0.f,0.f,0.f,0.f);

    int i = start;
    for (; i + 1 < end; i += 2) {
        const int pA = __ldg(&sorted[i]);
        const int pB = __ldg(&sorted[i + 1]);
        const int sA = pA & 0x1FFFF, rA = pA >> 17;
        const int sB = pB & 0x1FFFF, rB = pB >> 17;
        const float4 rvA = r4[rA * 32 + lane];
        const float4 m0A = m4[sA * 32 + lane];
        const float4 m1A = m4[ND4 + sA * 32 + lane];
        const float4 rvB = r4[rB * 32 + lane];
        const float4 m0B = m4[sB * 32 + lane];
        const float4 m1B = m4[ND4 + sB * 32 + lane];
        a0.x = fmaf(m0A.x, rvA.x, a0.x); a0.y = fmaf(m0A.y, rvA.y, a0.y);
        a0.z = fmaf(m0A.z, rvA.z, a0.z); a0.w = fmaf(m0A.w, rvA.w, a0.w);
        a1.x = fmaf(m1A.x, rvA.x, a1.x); a1.y = fmaf(m1A.y, rvA.y, a1.y);
        a1.z = fmaf(m1A.z, rvA.z, a1.z); a1.w = fmaf(m1A.w, rvA.w, a1.w);
        a0.x = fmaf(m0B.x, rvB.x, a0.x); a0.y = fmaf(m0B.y, rvB.y, a0.y);
        a0.z = fmaf(m0B.z, rvB.z, a0.z); a0.w = fmaf(m0B.w, rvB.w, a0.w);
        a1.x = fmaf(m1B.x, rvB.x, a1.x); a1.y = fmaf(m1B.y, rvB.y, a1.y);
        a1.z = fmaf(m1B.z, rvB.z, a1.z); a1.w = fmaf(m1B.w, rvB.w, a1.w);
    }
    if (i < end) {
        const int p = __ldg(&sorted[i]);
        const int s = p & 0x1FFFF, r = p >> 17;
        const float4 rv = r4[r * 32 + lane];
        const float4 m0 = m4[s * 32 + lane];
        const float4 m1 = m4[ND4 + s * 32 + lane];
        a0.x = fmaf(m0.x, rv.x, a0.x); a0.y = fmaf(m0.y, rv.y, a0.y);
        a0.z = fmaf(m0.z, rv.z, a0.z); a0.w = fmaf(m0.w, rv.w, a0.w);
        a1.x = fmaf(m1.x, rv.x, a1.x); a1.y = fmaf(m1.y, rv.y, a1.y);
        a1.z = fmaf(m1.z, rv.z, a1.z); a1.w = fmaf(m1.w, rv.w, a1.w);
    }

    // write packed bf16 hi/lo (same split the update staging used to do)
    const int NDp = (ND / DD) * 64;          // N * 64 pairs
    uint32_t h0, l0, h1, l1;
    split_bf16_pair(a0.x, a0.y, h0, l0);
    split_bf16_pair(a0.z, a0.w, h1, l1);
    *(uint2*)&aggh[nid * 64 + lane * 2] = make_uint2(h0, h1);
    *(uint2*)&aggl[nid * 64 + lane * 2] = make_uint2(l0, l1);
    split_bf16_pair(a1.x, a1.y, h0, l0);
    split_bf16_pair(a1.z, a1.w, h1, l1);
    *(uint2*)&aggh[NDp + nid * 64 + lane * 2] = make_uint2(h0, h1);
    *(uint2*)&aggl[NDp + nid * 64 + lane * 2] = make_uint2(l0, l1);
}

// ============================================================================
// Kernel 3: upd = relu([h|agg] @ W_upd^T + b); out = LN(h + upd)
// bf16x3; prepacked W + prepacked agg; chunks 0-3: h (split), 4-7: agg (copy)
// ============================================================================
__global__ __launch_bounds__(256) void update_ln_mma(
    const float* __restrict__ h,
    const uint32_t* __restrict__ aggh, const uint32_t* __restrict__ aggl,
    const uint32_t* __restrict__ Wh, const uint32_t* __restrict__ Wl,
    const float* __restrict__ bupd,
    const float* __restrict__ lns, const float* __restrict__ lnb,
    float* __restrict__ out, int rows)
{
    extern __shared__ uint32_t sm[];
    uint32_t* Ash = sm + OF_ASH;
    uint32_t* Asl = sm + OF_ASL;
    uint32_t* Bsh = sm + OF_BSH;
    uint32_t* Bsl = sm + OF_BSL;

    const int tid = threadIdx.x;
    const int lane = tid & 31, wid = tid >> 5;
    const int g = lane >> 2, q = lane & 3;
    const int m0 = (wid >> 2) * 32, n0 = (wid & 3) * 32;
    const int warp_n = wid & 3;
    const int row0 = blockIdx.x * 64;

    const float4* h4 = (const float4*)h;

    float c[2][4][4];
    #pragma unroll
    for (int mt = 0; mt < 2; ++mt)
        #pragma unroll
        for (int nt = 0; nt < 4; ++nt)
            #pragma unroll
            for (int k = 0; k < 4; ++k) c[mt][nt][k] = 0.f;

    for (int ch = 0; ch < 8; ++ch) {
        if (ch < 4) {
            // A from h: split
            #pragma unroll
            for (int u = 0; u < 2; ++u) {
                const int i = tid + u * 256;
                const int gr = row0 + (i >> 3);
                float4 v = (gr < rows) ? h4[gr * 32 + ch * 8 + (i & 7)]
                                       : make_float4(0.f, 0.f, 0.f, 0.f);
                stage_split(Ash, Asl, i, v);
            }
        } else {
            // A from prepacked agg: copy
            const int pcol = (ch & 3) * 16;
            #pragma unroll
            for (int u = 0; u < 2; ++u) {
                const int i = tid + u * 256;
                const int gr = row0 + (i >> 3);
                const int j4 = i & 7;
                uint2 hh = make_uint2(0u, 0u), ll = make_uint2(0u, 0u);
                if (gr < rows) {
                    const int pidx = gr * 64 + pcol + j4 * 2;
                    hh = *(const uint2*)&aggh[pidx];
                    ll = *(const uint2*)&aggl[pidx];
                }
                stage_copy(Ash, Asl, i, hh, ll);
            }
        }
        // B from prepacked W_upd: copy
        #pragma unroll
        for (int u = 0; u < 4; ++u) {
            const int i = tid + u * 256;
            const int r = i >> 3, j4 = i & 7;
            const int pidx = r * 128 + ch * 16 + j4 * 2;
            stage_copy(Bsh, Bsl, i,
                       *(const uint2*)&Wh[pidx], *(const uint2*)&Wl[pidx]);
        }
        __syncthreads();
        mma_chunk(Ash, Asl, Bsh, Bsl, m0, n0, g, q, c);
        __syncthreads();
    }

    // ---- epilogue: v = relu(C + b) + h, LN across row ----
    float2* red = (float2*)sm;          // red[row(64)][warp_n(4)]

    float2 bias[4], lsc[4], lbi[4];
    #pragma unroll
    for (int nt = 0; nt < 4; ++nt) {
        const int col = n0 + nt * 8 + q * 2;
        bias[nt] = *(const float2*)&bupd[col];
        lsc[nt]  = *(const float2*)&lns[col];
        lbi[nt]  = *(const float2*)&lnb[col];
    }

    float s1v[2][2], s2v[2][2];
    #pragma unroll
    for (int mt = 0; mt < 2; ++mt) {
        const int rlo = row0 + m0 + mt * 16 + g;
        const int rhi = rlo + 8;
        float p1lo = 0.f, p2lo = 0.f, p1hi = 0.f, p2hi = 0.f;
        #pragma unroll
        for (int nt = 0; nt < 4; ++nt) {
            const int col = n0 + nt * 8 + q * 2;
            float2 hlo = (rlo < rows) ? *(const float2*)&h[rlo * DD + col]
                                      : make_float2(0.f, 0.f);
            float2 hhi = (rhi < rows) ? *(const float2*)&h[rhi * DD + col]
                                      : make_float2(0.f, 0.f);
            float v0 = fmaxf(c[mt][nt][0] + bias[nt].x, 0.f) + hlo.x;
            float v1 = fmaxf(c[mt][nt][1] + bias[nt].y, 0.f) + hlo.y;
            float v2 = fmaxf(c[mt][nt][2] + bias[nt].x, 0.f) + hhi.x;
            float v3 = fmaxf(c[mt][nt][3] + bias[nt].y, 0.f) + hhi.y;
            c[mt][nt][0] = v0; c[mt][nt][1] = v1;
            c[mt][nt][2] = v2; c[mt][nt][3] = v3;
            p1lo += v0 + v1;  p2lo += v0*v0 + v1*v1;
            p1hi += v2 + v3;  p2hi += v2*v2 + v3*v3;
        }
        s1v[mt][0] = p1lo; s2v[mt][0] = p2lo;
        s1v[mt][1] = p1hi; s2v[mt][1] = p2hi;
    }
    #pragma unroll
    for (int mt = 0; mt < 2; ++mt)
        #pragma unroll
        for (int hf = 0; hf < 2; ++hf) {
            float s1 = s1v[mt][hf], s2 = s2v[mt][hf];
            s1 += __shfl_xor_sync(0xffffffffu, s1, 1);
            s2 += __shfl_xor_sync(0xffffffffu, s2, 1);
            s1 += __shfl_xor_sync(0xffffffffu, s1, 2);
            s2 += __shfl_xor_sync(0xffffffffu, s2, 2);
            if (q == 0) {
                const int rl = m0 + mt * 16 + hf * 8 + g;
                red[rl * 4 + warp_n] = make_float2(s1, s2);
            }
        }
    __syncthreads();

    #pragma unroll
    for (int mt = 0; mt < 2; ++mt) {
        #pragma unroll
        for (int hf = 0; hf < 2; ++hf) {
            const int rl = m0 + mt * 16 + hf * 8 + g;
            const int gr = row0 + rl;
            float S1 = 0.f, S2 = 0.f;
            #pragma unroll
            for (int w = 0; w < 4; ++w) {
                float2 p = red[rl * 4 + w];
                S1 += p.x; S2 += p.y;
            }
            const float mu  = S1 * (1.f / 128.f);
            const float var = S2 * (1.f / 128.f) - mu * mu;
            const float rs  = rsqrtf(var + 1e-5f);
            if (gr < rows) {
                #pragma unroll
                for (int nt = 0; nt < 4; ++nt) {
                    const int col = n0 + nt * 8 + q * 2;
                    const float v0 = c[mt][nt][hf * 2 + 0];
                    const float v1 = c[mt][nt][hf * 2 + 1];
                    float2 o;
                    o.x = (v0 - mu) * rs * lsc[nt].x + lbi[nt].x;
                    o.y = (v1 - mu) * rs * lsc[nt].y + lbi[nt].y;
                    *(float2*)&out[gr * DD + col] = o;
                }
            }
        }
    }
}

// ============================================================================
// host
// ============================================================================
extern "C" void kernel_launch(void* const* d_in, const int* in_sizes, int n_in,
                              void* d_out, int out_size)
{
    const float* h    = (const float*)d_in[0];
    const float* Wmsg = (const float*)d_in[1];
    const float* rel  = (const float*)d_in[2];
    const float* Wupd = (const float*)d_in[3];
    const float* bupd = (const float*)d_in[4];
    const float* lns  = (const float*)d_in[5];
    const float* lnb  = (const float*)d_in[6];
    const int*   esrc = (const int*)d_in[7];
    const int*   etgt = (const int*)d_in[8];
    const int*   erel = (const int*)d_in[9];
    float* out = (float*)d_out;

    const int E    = in_sizes[7];
    const int rows = in_sizes[0] / DD;     // B*N
    const int N    = rows / 2;
    const int ND   = N * DD;
    const int tiles = (rows + 63) / 64;

    void *pm, *pah, *pal, *pc, *pb, *ps, *pwmh, *pwml, *pwuh, *pwul;
    cudaGetSymbolAddress(&pm, g_m);
    cudaGetSymbolAddress(&pah, g_agg_h);
    cudaGetSymbolAddress(&pal, g_agg_l);
    cudaGetSymbolAddress(&pc, g_cnt);
    cudaGetSymbolAddress(&pb, g_base);
    cudaGetSymbolAddress(&ps, g_sorted);
    cudaGetSymbolAddress(&pwmh, g_Wm_h);
    cudaGetSymbolAddress(&pwml, g_Wm_l);
    cudaGetSymbolAddress(&pwuh, g_Wu_h);
    cudaGetSymbolAddress(&pwul, g_Wu_l);
    float*    d_m    = (float*)pm;
    uint32_t* d_aggh = (uint32_t*)pah;
    uint32_t* d_aggl = (uint32_t*)pal;
    int*      d_cnt  = (int*)pc;
    int*      d_base = (int*)pb;
    int*      d_sort = (int*)ps;
    uint32_t* d_wmh  = (uint32_t*)pwmh;
    uint32_t* d_wml  = (uint32_t*)pwml;
    uint32_t* d_wuh  = (uint32_t*)pwuh;
    uint32_t* d_wul  = (uint32_t*)pwul;

    cudaFuncSetAttribute(msg_gemm_mma,
        cudaFuncAttributeMaxDynamicSharedMemorySize, SM_BYTES);
    cudaFuncSetAttribute(update_ln_mma,
        cudaFuncAttributeMaxDynamicSharedMemorySize, SM_BYTES);

    // pre-split weights (tiny)
    presplit_k<<<96, 256>>>(Wmsg, Wupd, d_wmh, d_wml, d_wuh, d_wul);

    // edge sort (counting sort by target)
    cudaMemsetAsync(d_cnt, 0, (size_t)N * sizeof(int), 0);
    hist_k<<<(E + 255) / 256, 256>>>(etgt, d_cnt, E);
    exscan_k<<<1, 1024>>>(d_cnt, d_base, N);
    fill_k<<<(E + 255) / 256, 256>>>(esrc, etgt, erel, d_base, d_sort, E);

    // m = h @ W_msg^T
    msg_gemm_mma<<<tiles, 256, SM_BYTES>>>(h, d_wmh, d_wml, d_m, rows);

    // agg[t] = sum_{e: tgt=t} m[src_e] * rel_emb[rel_e]  (packed bf16 out)
    gather_csr<<<(N + 7) / 8, 256>>>(d_m, rel, d_base, d_sort,
                                     d_aggh, d_aggl, N, ND);

    // update + residual + layernorm
    update_ln_mma<<<tiles, 256, SM_BYTES>>>(h, d_aggh, d_aggl, d_wuh, d_wul,
                                            bupd, lns, lnb, out, rows);
}